// round 12
// baseline (speedup 1.0000x reference)
#include <cuda_runtime.h>

#define BB 4
#define CC 32
#define NF 40000
#define NE 80000
#define NV 40000
#define CAP 32          // max bucketed edges per dst node (avg deg 2-6; P(>32)~1e-15)

// cnt layout: [f2e: NE][e2v: NV][ff: NF][e2f: NF][v2e: NE]
#define CNT_TOT (NE + NV + NF + NF + NE)
#define OFF_F2E 0
#define OFF_E2V (NE)
#define OFF_FF  (NE + NV)
#define OFF_E2F (NE + NV + NF)
#define OFF_V2E (NE + NV + NF + NF)

// Interleaved feature layout: [node][channel][batch], i.e. float4 per (node,channel).
__device__ float4 g_xf0[NF * CC];
__device__ float4 g_xe0[NE * CC];
__device__ float4 g_xv0[NV * CC];
__device__ float4 g_xe1[NE * CC];   // F2E output
__device__ float4 g_xf1[NF * CC];   // FF output
__device__ float4 g_xv1[NV * CC];   // E2V output (interleaved mirror for V2E src)
__device__ int    g_cnt[CNT_TOT];
__device__ int    g_bucket[(size_t)CNT_TOT * CAP];

__device__ __forceinline__ unsigned long long ffma2(
    unsigned long long a, unsigned long long b, unsigned long long c) {
    unsigned long long d;
    asm("fma.rn.f32x2 %0, %1, %2, %3;" : "=l"(d) : "l"(a), "l"(b), "l"(c));
    return d;
}
__device__ __forceinline__ unsigned long long pack2(float lo, float hi) {
    unsigned long long u;
    asm("mov.b64 %0, {%1, %2};" : "=l"(u) : "f"(lo), "f"(hi));
    return u;
}
__device__ __forceinline__ void unpack2(unsigned long long u, float& lo, float& hi) {
    asm("mov.b64 {%0, %1}, %2;" : "=f"(lo), "=f"(hi) : "l"(u));
}
__device__ __forceinline__ float4 min4(float4 a, float4 b) {
    return make_float4(fminf(a.x, b.x), fminf(a.y, b.y),
                       fminf(a.z, b.z), fminf(a.w, b.w));
}

// out interleaved: warp per (batch,node), lane = channel; scalar store into float4 slot.
template <int CIN>
__global__ void embed_kernel(const float* __restrict__ x, const float* __restrict__ W,
                             const float* __restrict__ bias, float* __restrict__ outI,
                             int nNodes) {
    int t = blockIdx.x * blockDim.x + threadIdx.x;
    int w = t >> 5, c = t & 31;
    if (w >= BB * nNodes) return;
    int b = w / nNodes;
    int node = w - b * nNodes;
    float acc = bias[c];
#pragma unroll
    for (int k = 0; k < CIN; ++k)
        acc += x[(size_t)w * CIN + k] * W[k * CC + c];
    float v = acc > 0.f ? acc : 0.01f * acc;
    outI[((size_t)node * CC + c) * BB + b] = v;
}

__global__ void zero_cnt_kernel(int* __restrict__ cnt, int n4) {
    int i = blockIdx.x * blockDim.x + threadIdx.x;
    if (i < n4) reinterpret_cast<int4*>(cnt)[i] = make_int4(0, 0, 0, 0);
}

// 4 edges per thread via int4 (all E are divisible by 4).
__global__ void fill_kernel(const int* __restrict__ edges, int E,
                            int* __restrict__ cnt, int* __restrict__ bucket) {
    int i0 = (blockIdx.x * blockDim.x + threadIdx.x) * 4;
    if (i0 >= E) return;
    int4 s4 = *reinterpret_cast<const int4*>(edges + i0);
    int4 d4 = *reinterpret_cast<const int4*>(edges + E + i0);
    int ss[4] = {s4.x, s4.y, s4.z, s4.w};
    int dd[4] = {d4.x, d4.y, d4.z, d4.w};
#pragma unroll
    for (int j = 0; j < 4; ++j) {
        int slot = atomicAdd(&cnt[dd[j]], 1);
        if (slot < CAP) bucket[(size_t)dd[j] * CAP + slot] = ss[j];
    }
}

// Fused segment-min gather + residual MLP, interleaved [node][c][batch] features.
// Block = 64 nodes (8 per warp). One LDG.128 per (edge,lane) covers all 4 batches.
// Chain-head (cnt + first bucket chunk) prefetched for the next node.
//   maxes[b,c] = (empty) ? 0 : x_dst[b,c] - min_src[b,c]
//   out[b,:]   = x_dst + leaky_relu(concat(x_dst, maxes) @ W[64,32] + bias)
// outC: canonical [b][node][c] (nullable). outI: interleaved (nullable).
__global__ __launch_bounds__(256, 4) void reduce_mlp_kernel(
    const int* __restrict__ cnt, const int* __restrict__ bucket,
    const float4* __restrict__ xs4, const float4* __restrict__ xd4,
    const float* __restrict__ W, const float* __restrict__ bias,
    float* __restrict__ outC, float4* __restrict__ outI, int Nd) {
    __shared__ unsigned long long sWp[CC][CC];       // [k][lane] = (W[k][lane], W[k+32][lane])
    __shared__ __align__(16) float2 stage[8][BB][CC];// [warp][batch][k]
    int tid = threadIdx.x;
    int lane = tid & 31, wip = tid >> 5;

    for (int k = wip; k < CC; k += 8)
        sWp[k][lane] = pack2(W[k * CC + lane], W[(k + CC) * CC + lane]);
    __syncthreads();

    float bv = bias[lane];
    const float PINF = __int_as_float(0x7f800000);

    int dBase = blockIdx.x * 64 + wip * 8;

    // Prefetch chain-head for the first node.
    int degN = 0;
    int4 qN = make_int4(0, 0, 0, 0);
    if (dBase < Nd) {
        degN = cnt[dBase];
        qN = *reinterpret_cast<const int4*>(bucket + (size_t)dBase * CAP);
    }

#pragma unroll 1
    for (int it = 0; it < 8; ++it) {
        int d = dBase + it;
        if (d >= Nd) break;

        int deg = degN;
        if (deg > CAP) deg = CAP;
        int4 qA = qN;

        if (it < 7 && d + 1 < Nd) {
            degN = cnt[d + 1];
            qN = *reinterpret_cast<const int4*>(bucket + (size_t)(d + 1) * CAP);
        }

        // x_dst (all 4 batches in one LDG.128), independent of bucket chain.
        float4 xv4 = xd4[(size_t)d * CC + lane];

        // ---- segment-min gather: 1 LDG.128 per edge per lane ----
        const int* bk = bucket + (size_t)d * CAP;
        float4 mn4 = make_float4(PINF, PINF, PINF, PINF);
        int i = 0;
        if (deg >= 4) {
            int4 q = qA;
            for (;;) {
                float4 v0 = xs4[(size_t)q.x * CC + lane];
                float4 v1 = xs4[(size_t)q.y * CC + lane];
                float4 v2 = xs4[(size_t)q.z * CC + lane];
                float4 v3 = xs4[(size_t)q.w * CC + lane];
                mn4 = min4(mn4, min4(min4(v0, v1), min4(v2, v3)));
                i += 4;
                if (i + 4 > deg) break;
                q = *reinterpret_cast<const int4*>(bk + i);
            }
        }
        for (; i < deg; ++i) {
            int s = bk[i];
            mn4 = min4(mn4, xs4[(size_t)s * CC + lane]);
        }

        // ---- stage h = (xv, mv) per batch ----
        float xvA[BB] = {xv4.x, xv4.y, xv4.z, xv4.w};
        float mnA[BB] = {mn4.x, mn4.y, mn4.z, mn4.w};
#pragma unroll
        for (int b = 0; b < BB; ++b) {
            float m = mnA[b];
            float mv = (__float_as_uint(m) == 0x7f800000u) ? 0.f : xvA[b] - m;
            stage[wip][b][lane] = make_float2(xvA[b], mv);
        }
        __syncwarp();

        // ---- MLP: register-tile 4 W pairs; h via LDS.128 broadcast ----
        unsigned long long acc0[BB], acc1[BB];
#pragma unroll
        for (int b = 0; b < BB; ++b) { acc0[b] = 0ull; acc1[b] = 0ull; }
#pragma unroll
        for (int kt = 0; kt < CC; kt += 4) {
            unsigned long long w0 = sWp[kt][lane],     w1 = sWp[kt + 1][lane];
            unsigned long long w2 = sWp[kt + 2][lane], w3 = sWp[kt + 3][lane];
#pragma unroll
            for (int b = 0; b < BB; ++b) {
                const ulonglong2* hp2 =
                    reinterpret_cast<const ulonglong2*>(stage[wip][b]);
                ulonglong2 h01 = hp2[kt / 2];
                ulonglong2 h23 = hp2[kt / 2 + 1];
                acc0[b] = ffma2(h01.x, w0, acc0[b]);
                acc1[b] = ffma2(h01.y, w1, acc1[b]);
                acc0[b] = ffma2(h23.x, w2, acc0[b]);
                acc1[b] = ffma2(h23.y, w3, acc1[b]);
            }
        }
        float o[BB];
#pragma unroll
        for (int b = 0; b < BB; ++b) {
            float l0, h0, l1, h1;
            unpack2(acc0[b], l0, h0);
            unpack2(acc1[b], l1, h1);
            float acc = ((l0 + h0) + (l1 + h1)) + bv;
            o[b] = xvA[b] + (acc > 0.f ? acc : 0.01f * acc);
        }
        if (outC) {
#pragma unroll
            for (int b = 0; b < BB; ++b)
                outC[((size_t)b * Nd + d) * CC + lane] = o[b];
        }
        if (outI)
            outI[(size_t)d * CC + lane] = make_float4(o[0], o[1], o[2], o[3]);
        __syncwarp();
    }
}

static inline int cdiv(long long a, int b) { return (int)((a + b - 1) / b); }

extern "C" void kernel_launch(void* const* d_in, const int* in_sizes, int n_in,
                              void* d_out, int out_size) {
    const float* x_f = (const float*)d_in[0];
    const float* x_e = (const float*)d_in[1];
    const float* x_v = (const float*)d_in[2];
    // d_in[3] = index_id (identity arange; unused)
    const int* fe = (const int*)d_in[4];
    const int* ev = (const int*)d_in[5];
    const int* ff = (const int*)d_in[6];
    const int* ef = (const int*)d_in[7];
    const int* ve = (const int*)d_in[8];
    const float* Wf = (const float*)d_in[9];   const float* bf = (const float*)d_in[10];
    const float* We = (const float*)d_in[11];  const float* be = (const float*)d_in[12];
    const float* Wv = (const float*)d_in[13];  const float* bv = (const float*)d_in[14];
    const float* W_f2e = (const float*)d_in[15]; const float* b_f2e = (const float*)d_in[16];
    const float* W_e2v = (const float*)d_in[17]; const float* b_e2v = (const float*)d_in[18];
    const float* W_ff  = (const float*)d_in[19]; const float* b_ff  = (const float*)d_in[20];
    const float* W_e2f = (const float*)d_in[21]; const float* b_e2f = (const float*)d_in[22];
    const float* W_v2e = (const float*)d_in[23]; const float* b_v2e = (const float*)d_in[24];

    int E_fe = in_sizes[4] / 2, E_ev = in_sizes[5] / 2, E_ff = in_sizes[6] / 2,
        E_ef = in_sizes[7] / 2, E_ve = in_sizes[8] / 2;

    float* out_xf = (float*)d_out;
    float* out_xe = out_xf + (size_t)BB * NF * CC;
    float* out_xv = out_xe + (size_t)BB * NE * CC;

    float4 *xf0, *xe0, *xv0, *xe1, *xf1, *xv1;
    int *cnt, *bucket;
    cudaGetSymbolAddress((void**)&xf0, g_xf0);
    cudaGetSymbolAddress((void**)&xe0, g_xe0);
    cudaGetSymbolAddress((void**)&xv0, g_xv0);
    cudaGetSymbolAddress((void**)&xe1, g_xe1);
    cudaGetSymbolAddress((void**)&xf1, g_xf1);
    cudaGetSymbolAddress((void**)&xv1, g_xv1);
    cudaGetSymbolAddress((void**)&cnt, g_cnt);
    cudaGetSymbolAddress((void**)&bucket, g_bucket);

    const int TB = 256;

    // ---- zero ALL counters once, then build all 5 buckets up front ----
    zero_cnt_kernel<<<cdiv(CNT_TOT / 4, TB), TB>>>(cnt, CNT_TOT / 4);
    fill_kernel<<<cdiv(E_fe / 4, TB), TB>>>(fe, E_fe, cnt + OFF_F2E, bucket + (size_t)OFF_F2E * CAP);
    fill_kernel<<<cdiv(E_ev / 4, TB), TB>>>(ev, E_ev, cnt + OFF_E2V, bucket + (size_t)OFF_E2V * CAP);
    fill_kernel<<<cdiv(E_ff / 4, TB), TB>>>(ff, E_ff, cnt + OFF_FF,  bucket + (size_t)OFF_FF  * CAP);
    fill_kernel<<<cdiv(E_ef / 4, TB), TB>>>(ef, E_ef, cnt + OFF_E2F, bucket + (size_t)OFF_E2F * CAP);
    fill_kernel<<<cdiv(E_ve / 4, TB), TB>>>(ve, E_ve, cnt + OFF_V2E, bucket + (size_t)OFF_V2E * CAP);

    // ---- input embeddings (interleaved outputs) ----
    embed_kernel<4><<<cdiv((long long)BB * NF * 32, TB), TB>>>(x_f, Wf, bf, (float*)xf0, NF);
    embed_kernel<6><<<cdiv((long long)BB * NE * 32, TB), TB>>>(x_e, We, be, (float*)xe0, NE);
    embed_kernel<3><<<cdiv((long long)BB * NV * 32, TB), TB>>>(x_v, Wv, bv, (float*)xv0, NV);

    // ---- layers ----
    // F2E: src xf0, dst xe0 -> xe1 (interleaved only)
    reduce_mlp_kernel<<<cdiv(NE, 64), 256>>>(cnt + OFF_F2E, bucket + (size_t)OFF_F2E * CAP,
                                             xf0, xe0, W_f2e, b_f2e, nullptr, xe1, NE);
    // E2V: src xe0, dst xv0 -> out_xv (canonical) + xv1 (interleaved, for V2E src)
    reduce_mlp_kernel<<<cdiv(NV, 64), 256>>>(cnt + OFF_E2V, bucket + (size_t)OFF_E2V * CAP,
                                             xe0, xv0, W_e2v, b_e2v, out_xv, xv1, NV);
    // FF: src xf0, dst xf0 -> xf1 (interleaved only)
    reduce_mlp_kernel<<<cdiv(NF, 64), 256>>>(cnt + OFF_FF, bucket + (size_t)OFF_FF * CAP,
                                             xf0, xf0, W_ff, b_ff, nullptr, xf1, NF);
    // E2F: src xe1, dst xf1 -> out_xf (canonical only)
    reduce_mlp_kernel<<<cdiv(NF, 64), 256>>>(cnt + OFF_E2F, bucket + (size_t)OFF_E2F * CAP,
                                             xe1, xf1, W_e2f, b_e2f, out_xf, nullptr, NF);
    // V2E: src xv1, dst xe1 -> out_xe (canonical only)
    reduce_mlp_kernel<<<cdiv(NE, 64), 256>>>(cnt + OFF_V2E, bucket + (size_t)OFF_V2E * CAP,
                                             xv1, xe1, W_v2e, b_v2e, out_xe, nullptr, NE);
}

// round 13
// speedup vs baseline: 1.0577x; 1.0577x over previous
#include <cuda_runtime.h>

#define BB 4
#define CC 32
#define NF 40000
#define NE 80000
#define NV 40000
#define CAP 32          // bucket row = 32 ints = exactly one warp-coalesced load

// cnt layout: [f2e: NE][e2v: NV][ff: NF][e2f: NF][v2e: NE]
#define CNT_TOT (NE + NV + NF + NF + NE)
#define OFF_F2E 0
#define OFF_E2V (NE)
#define OFF_FF  (NE + NV)
#define OFF_E2F (NE + NV + NF)
#define OFF_V2E (NE + NV + NF + NF)

// Persistent scratch (no allocations anywhere); canonical [b][node][c] layout.
__device__ float g_xf0[BB * NF * CC];
__device__ float g_xe0[BB * NE * CC];
__device__ float g_xv0[BB * NV * CC];
__device__ float g_xe1[BB * NE * CC];   // F2E output
__device__ float g_xf1[BB * NF * CC];   // FF output
__device__ int   g_cnt[CNT_TOT];
__device__ int   g_bucket[(size_t)CNT_TOT * CAP];

__device__ __forceinline__ unsigned long long ffma2(
    unsigned long long a, unsigned long long b, unsigned long long c) {
    unsigned long long d;
    asm("fma.rn.f32x2 %0, %1, %2, %3;" : "=l"(d) : "l"(a), "l"(b), "l"(c));
    return d;
}
__device__ __forceinline__ unsigned long long pack2(float lo, float hi) {
    unsigned long long u;
    asm("mov.b64 %0, {%1, %2};" : "=l"(u) : "f"(lo), "f"(hi));
    return u;
}
__device__ __forceinline__ void unpack2(unsigned long long u, float& lo, float& hi) {
    asm("mov.b64 {%0, %1}, %2;" : "=f"(lo), "=f"(hi) : "l"(u));
}

// out[b,n,c] = leaky_relu(x[b,n,:] @ W + bias), warp per node, lane = channel.
template <int CIN>
__global__ void embed_kernel(const float* __restrict__ x, const float* __restrict__ W,
                             const float* __restrict__ bias, float* __restrict__ out,
                             int nNodes) {
    int t = blockIdx.x * blockDim.x + threadIdx.x;
    int node = t >> 5, c = t & 31;
    if (node >= nNodes) return;
    float acc = bias[c];
#pragma unroll
    for (int k = 0; k < CIN; ++k)
        acc += x[node * CIN + k] * W[k * CC + c];
    out[t] = acc > 0.f ? acc : 0.01f * acc;
}

__global__ void zero_cnt_kernel(int* __restrict__ cnt, int n4) {
    int i = blockIdx.x * blockDim.x + threadIdx.x;
    if (i < n4) reinterpret_cast<int4*>(cnt)[i] = make_int4(0, 0, 0, 0);
}

// All 5 edge lists in one launch. Block-range if/else with SCALAR pointers
// (no runtime-indexed arrays -> no local-memory spill). 4 edges per thread.
__global__ void fill_all_kernel(
    const int* eA, int EA, int offA, int bA,   // block-range starts b*
    const int* eB, int EB, int offB, int bB,
    const int* eC, int EC, int offC, int bC,
    const int* eD, int ED, int offD, int bD,
    const int* eE, int EE, int offE,
    int* __restrict__ cnt, int* __restrict__ bucket) {
    int blk = blockIdx.x;
    const int* eg; int E; int off; int blk0;
    if      (blk < bB) { eg = eA; E = EA; off = offA; blk0 = bA; }
    else if (blk < bC) { eg = eB; E = EB; off = offB; blk0 = bB; }
    else if (blk < bD) { eg = eC; E = EC; off = offC; blk0 = bC; }
    else if (blk < bD + ((ED / 4 + 255) / 256)) { eg = eD; E = ED; off = offD; blk0 = bD; }
    else { eg = eE; E = EE; off = offE; blk0 = bD + ((ED / 4 + 255) / 256); }
    int i0 = ((blk - blk0) * 256 + threadIdx.x) * 4;
    if (i0 >= E) return;
    int4 s4 = *reinterpret_cast<const int4*>(eg + i0);
    int4 d4 = *reinterpret_cast<const int4*>(eg + E + i0);
    int ss[4] = {s4.x, s4.y, s4.z, s4.w};
    int dd[4] = {d4.x, d4.y, d4.z, d4.w};
#pragma unroll
    for (int j = 0; j < 4; ++j) {
        int d = off + dd[j];
        int slot = atomicAdd(&cnt[d], 1);
        if (slot < CAP) bucket[(size_t)d * CAP + slot] = ss[j];
    }
}

// Fused segment-min gather + residual MLP. Block = 64 nodes (8 per warp).
// Bucket row (32 ints) loaded as ONE warp-coalesced LDG per node; src indices
// distributed via shfl -> all feature gathers are issueable with no intervening
// memory dependency. Next node's cnt + bucket row prefetched.
//   maxes[b,c] = (empty) ? 0 : x_dst[b,c] - min_src[b,c]
//   out[b,:]   = x_dst + leaky_relu(concat(x_dst, maxes) @ W[64,32] + bias)
__global__ __launch_bounds__(256, 4) void reduce_mlp_kernel(
    const int* __restrict__ cnt, const int* __restrict__ bucket,
    const float* __restrict__ xs, const float* __restrict__ xd,
    const float* __restrict__ W, const float* __restrict__ bias,
    float* __restrict__ out, int Ns, int Nd) {
    __shared__ unsigned long long sWp[CC][CC];       // [k][lane] = (W[k][lane], W[k+32][lane])
    __shared__ __align__(16) float2 stage[8][BB][CC];// [warp][batch][k]
    int tid = threadIdx.x;
    int lane = tid & 31, wip = tid >> 5;

    for (int k = wip; k < CC; k += 8)
        sWp[k][lane] = pack2(W[k * CC + lane], W[(k + CC) * CC + lane]);
    __syncthreads();

    float bv = bias[lane];
    const size_t BS = (size_t)Ns * CC;   // batch stride in xs
    const float PINF = __int_as_float(0x7f800000);

    int dBase = blockIdx.x * 64 + wip * 8;

    // Prefetch chain-head (deg + whole bucket row) for the first node.
    int degN = 0, bkvN = 0;
    if (dBase < Nd) {
        degN = cnt[dBase];
        bkvN = bucket[(size_t)dBase * CAP + lane];
    }

#pragma unroll 1
    for (int it = 0; it < 8; ++it) {
        int d = dBase + it;
        if (d >= Nd) break;

        int deg = degN;
        if (deg > CAP) deg = CAP;
        int bkv = bkvN;

        // Prefetch next node's chain-head (overlaps this node's gather/MLP).
        if (it < 7 && d + 1 < Nd) {
            degN = cnt[d + 1];
            bkvN = bucket[(size_t)(d + 1) * CAP + lane];
        }

        // x_dst loads (independent) issued early.
        float xv[BB];
#pragma unroll
        for (int b = 0; b < BB; ++b)
            xv[b] = xd[((size_t)b * Nd + d) * CC + lane];

        // ---- segment-min gather: src indices via shfl, all LDGs independent ----
        float mn0 = PINF, mn1 = PINF, mn2 = PINF, mn3 = PINF;
        int i = 0;
        for (; i + 4 <= deg; i += 4) {
            int s0 = __shfl_sync(0xffffffffu, bkv, i);
            int s1 = __shfl_sync(0xffffffffu, bkv, i + 1);
            int s2 = __shfl_sync(0xffffffffu, bkv, i + 2);
            int s3 = __shfl_sync(0xffffffffu, bkv, i + 3);
            const float* p0 = xs + (size_t)s0 * CC + lane;
            const float* p1 = xs + (size_t)s1 * CC + lane;
            const float* p2 = xs + (size_t)s2 * CC + lane;
            const float* p3 = xs + (size_t)s3 * CC + lane;
            float a0 = p0[0],      a1 = p1[0],      a2 = p2[0],      a3 = p3[0];
            float b0 = p0[BS],     b1 = p1[BS],     b2 = p2[BS],     b3 = p3[BS];
            float c0 = p0[2 * BS], c1 = p1[2 * BS], c2 = p2[2 * BS], c3 = p3[2 * BS];
            float e0 = p0[3 * BS], e1 = p1[3 * BS], e2 = p2[3 * BS], e3 = p3[3 * BS];
            mn0 = fminf(mn0, fminf(fminf(a0, a1), fminf(a2, a3)));
            mn1 = fminf(mn1, fminf(fminf(b0, b1), fminf(b2, b3)));
            mn2 = fminf(mn2, fminf(fminf(c0, c1), fminf(c2, c3)));
            mn3 = fminf(mn3, fminf(fminf(e0, e1), fminf(e2, e3)));
        }
        for (; i < deg; ++i) {
            int s = __shfl_sync(0xffffffffu, bkv, i);
            const float* p = xs + (size_t)s * CC + lane;
            mn0 = fminf(mn0, p[0]);
            mn1 = fminf(mn1, p[BS]);
            mn2 = fminf(mn2, p[2 * BS]);
            mn3 = fminf(mn3, p[3 * BS]);
        }
        float mns[BB] = {mn0, mn1, mn2, mn3};

        // ---- stage h = (xv, mv) per batch ----
#pragma unroll
        for (int b = 0; b < BB; ++b) {
            float m = mns[b];
            float mv = (__float_as_uint(m) == 0x7f800000u) ? 0.f : xv[b] - m;
            stage[wip][b][lane] = make_float2(xv[b], mv);
        }
        __syncwarp();

        // ---- MLP: register-tile 4 W pairs; h via LDS.128 broadcast ----
        unsigned long long acc0[BB], acc1[BB];
#pragma unroll
        for (int b = 0; b < BB; ++b) { acc0[b] = 0ull; acc1[b] = 0ull; }
#pragma unroll
        for (int kt = 0; kt < CC; kt += 4) {
            unsigned long long w0 = sWp[kt][lane],     w1 = sWp[kt + 1][lane];
            unsigned long long w2 = sWp[kt + 2][lane], w3 = sWp[kt + 3][lane];
#pragma unroll
            for (int b = 0; b < BB; ++b) {
                const ulonglong2* hp2 =
                    reinterpret_cast<const ulonglong2*>(stage[wip][b]);
                ulonglong2 h01 = hp2[kt / 2];
                ulonglong2 h23 = hp2[kt / 2 + 1];
                acc0[b] = ffma2(h01.x, w0, acc0[b]);
                acc1[b] = ffma2(h01.y, w1, acc1[b]);
                acc0[b] = ffma2(h23.x, w2, acc0[b]);
                acc1[b] = ffma2(h23.y, w3, acc1[b]);
            }
        }
#pragma unroll
        for (int b = 0; b < BB; ++b) {
            float l0, h0, l1, h1;
            unpack2(acc0[b], l0, h0);
            unpack2(acc1[b], l1, h1);
            float acc = ((l0 + h0) + (l1 + h1)) + bv;
            float o = xv[b] + (acc > 0.f ? acc : 0.01f * acc);
            out[((size_t)b * Nd + d) * CC + lane] = o;
        }
        __syncwarp();
    }
}

static inline int cdiv(long long a, int b) { return (int)((a + b - 1) / b); }

extern "C" void kernel_launch(void* const* d_in, const int* in_sizes, int n_in,
                              void* d_out, int out_size) {
    const float* x_f = (const float*)d_in[0];
    const float* x_e = (const float*)d_in[1];
    const float* x_v = (const float*)d_in[2];
    // d_in[3] = index_id (identity arange; unused)
    const int* fe = (const int*)d_in[4];
    const int* ev = (const int*)d_in[5];
    const int* ff = (const int*)d_in[6];
    const int* ef = (const int*)d_in[7];
    const int* ve = (const int*)d_in[8];
    const float* Wf = (const float*)d_in[9];   const float* bf = (const float*)d_in[10];
    const float* We = (const float*)d_in[11];  const float* be = (const float*)d_in[12];
    const float* Wv = (const float*)d_in[13];  const float* bv = (const float*)d_in[14];
    const float* W_f2e = (const float*)d_in[15]; const float* b_f2e = (const float*)d_in[16];
    const float* W_e2v = (const float*)d_in[17]; const float* b_e2v = (const float*)d_in[18];
    const float* W_ff  = (const float*)d_in[19]; const float* b_ff  = (const float*)d_in[20];
    const float* W_e2f = (const float*)d_in[21]; const float* b_e2f = (const float*)d_in[22];
    const float* W_v2e = (const float*)d_in[23]; const float* b_v2e = (const float*)d_in[24];

    int E_fe = in_sizes[4] / 2, E_ev = in_sizes[5] / 2, E_ff = in_sizes[6] / 2,
        E_ef = in_sizes[7] / 2, E_ve = in_sizes[8] / 2;

    float* out_xf = (float*)d_out;
    float* out_xe = out_xf + (size_t)BB * NF * CC;
    float* out_xv = out_xe + (size_t)BB * NE * CC;

    float *xf0, *xe0, *xv0, *xe1, *xf1;
    int *cnt, *bucket;
    cudaGetSymbolAddress((void**)&xf0, g_xf0);
    cudaGetSymbolAddress((void**)&xe0, g_xe0);
    cudaGetSymbolAddress((void**)&xv0, g_xv0);
    cudaGetSymbolAddress((void**)&xe1, g_xe1);
    cudaGetSymbolAddress((void**)&xf1, g_xf1);
    cudaGetSymbolAddress((void**)&cnt, g_cnt);
    cudaGetSymbolAddress((void**)&bucket, g_bucket);

    const int TB = 256;

    // ---- zero all counters, then build all 5 buckets in ONE launch ----
    zero_cnt_kernel<<<cdiv(CNT_TOT / 4, TB), TB>>>(cnt, CNT_TOT / 4);
    int bA = 0;
    int bB = bA + cdiv(E_fe / 4, TB);
    int bC = bB + cdiv(E_ev / 4, TB);
    int bD = bC + cdiv(E_ff / 4, TB);
    int bE = bD + cdiv(E_ef / 4, TB);
    int bTot = bE + cdiv(E_ve / 4, TB);
    fill_all_kernel<<<bTot, TB>>>(
        fe, E_fe, OFF_F2E, bA,
        ev, E_ev, OFF_E2V, bB,
        ff, E_ff, OFF_FF,  bC,
        ef, E_ef, OFF_E2F, bD,
        ve, E_ve, OFF_V2E,
        cnt, bucket);

    // ---- input embeddings ----
    embed_kernel<4><<<cdiv((long long)BB * NF * 32, TB), TB>>>(x_f, Wf, bf, xf0, BB * NF);
    embed_kernel<6><<<cdiv((long long)BB * NE * 32, TB), TB>>>(x_e, We, be, xe0, BB * NE);
    embed_kernel<3><<<cdiv((long long)BB * NV * 32, TB), TB>>>(x_v, Wv, bv, xv0, BB * NV);

    // ---- layers ----
    reduce_mlp_kernel<<<cdiv(NE, 64), 256>>>(cnt + OFF_F2E, bucket + (size_t)OFF_F2E * CAP,
                                             xf0, xe0, W_f2e, b_f2e, xe1, NF, NE);
    reduce_mlp_kernel<<<cdiv(NV, 64), 256>>>(cnt + OFF_E2V, bucket + (size_t)OFF_E2V * CAP,
                                             xe0, xv0, W_e2v, b_e2v, out_xv, NE, NV);
    reduce_mlp_kernel<<<cdiv(NF, 64), 256>>>(cnt + OFF_FF, bucket + (size_t)OFF_FF * CAP,
                                             xf0, xf0, W_ff, b_ff, xf1, NF, NF);
    reduce_mlp_kernel<<<cdiv(NF, 64), 256>>>(cnt + OFF_E2F, bucket + (size_t)OFF_E2F * CAP,
                                             xe1, xf1, W_e2f, b_e2f, out_xf, NE, NF);
    reduce_mlp_kernel<<<cdiv(NE, 64), 256>>>(cnt + OFF_V2E, bucket + (size_t)OFF_V2E * CAP,
                                             out_xv, xe1, W_v2e, b_v2e, out_xe, NV, NE);
}

// round 14
// speedup vs baseline: 1.1485x; 1.0859x over previous
#include <cuda_runtime.h>

#define BB 4
#define CC 32
#define NF 40000
#define NE 80000
#define NV 40000
#define CAP 32          // bucket row = 32 ints = exactly one warp-coalesced load

// cnt layout: [f2e: NE][e2v: NV][ff: NF][e2f: NF][v2e: NE]
#define CNT_TOT (NE + NV + NF + NF + NE)
#define OFF_F2E 0
#define OFF_E2V (NE)
#define OFF_FF  (NE + NV)
#define OFF_E2F (NE + NV + NF)
#define OFF_V2E (NE + NV + NF + NF)

// Persistent scratch (no allocations anywhere); canonical [b][node][c] layout.
__device__ float g_xf0[BB * NF * CC];
__device__ float g_xe0[BB * NE * CC];
__device__ float g_xv0[BB * NV * CC];
__device__ float g_xe1[BB * NE * CC];   // F2E output
__device__ float g_xf1[BB * NF * CC];   // FF output
__device__ int   g_cnt[CNT_TOT];
__device__ int   g_bucket[(size_t)CNT_TOT * CAP];

__device__ __forceinline__ unsigned long long ffma2(
    unsigned long long a, unsigned long long b, unsigned long long c) {
    unsigned long long d;
    asm("fma.rn.f32x2 %0, %1, %2, %3;" : "=l"(d) : "l"(a), "l"(b), "l"(c));
    return d;
}
__device__ __forceinline__ unsigned long long pack2(float lo, float hi) {
    unsigned long long u;
    asm("mov.b64 %0, {%1, %2};" : "=l"(u) : "f"(lo), "f"(hi));
    return u;
}
__device__ __forceinline__ void unpack2(unsigned long long u, float& lo, float& hi) {
    asm("mov.b64 {%0, %1}, %2;" : "=f"(lo), "=f"(hi) : "l"(u));
}

__global__ void zero_cnt_kernel(int* __restrict__ cnt, int n4) {
    int i = blockIdx.x * blockDim.x + threadIdx.x;
    if (i < n4) reinterpret_cast<int4*>(cnt)[i] = make_int4(0, 0, 0, 0);
}

// All 5 edge lists in one launch. Block-range if/else with SCALAR pointers.
__global__ void fill_all_kernel(
    const int* eA, int EA, int offA, int bA,
    const int* eB, int EB, int offB, int bB,
    const int* eC, int EC, int offC, int bC,
    const int* eD, int ED, int offD, int bD,
    const int* eE, int EE, int offE,
    int* __restrict__ cnt, int* __restrict__ bucket) {
    int blk = blockIdx.x;
    const int* eg; int E; int off; int blk0;
    if      (blk < bB) { eg = eA; E = EA; off = offA; blk0 = bA; }
    else if (blk < bC) { eg = eB; E = EB; off = offB; blk0 = bB; }
    else if (blk < bD) { eg = eC; E = EC; off = offC; blk0 = bC; }
    else if (blk < bD + ((ED / 4 + 255) / 256)) { eg = eD; E = ED; off = offD; blk0 = bD; }
    else { eg = eE; E = EE; off = offE; blk0 = bD + ((ED / 4 + 255) / 256); }
    int i0 = ((blk - blk0) * 256 + threadIdx.x) * 4;
    if (i0 >= E) return;
    int4 s4 = *reinterpret_cast<const int4*>(eg + i0);
    int4 d4 = *reinterpret_cast<const int4*>(eg + E + i0);
    int ss[4] = {s4.x, s4.y, s4.z, s4.w};
    int dd[4] = {d4.x, d4.y, d4.z, d4.w};
#pragma unroll
    for (int j = 0; j < 4; ++j) {
        int d = off + dd[j];
        int slot = atomicAdd(&cnt[d], 1);
        if (slot < CAP) bucket[(size_t)d * CAP + slot] = ss[j];
    }
}

// 8 nodes per warp: 2 coalesced LDGs fetch 8*CIN inputs, distributed by
// compile-time shfl; W column + bias in registers (loaded once per warp).
template <int CIN>
__device__ __forceinline__ void embed_body(
    const float* __restrict__ x, const float* __restrict__ W,
    const float* __restrict__ bias, float* __restrict__ out,
    int warpInSeg, int tot /* BB*nNodes */, int lane) {
    int node0 = warpInSeg * 8;
    if (node0 >= tot) return;
    float Wr[CIN];
#pragma unroll
    for (int k = 0; k < CIN; ++k) Wr[k] = W[k * CC + lane];
    float bv = bias[lane];

    const float* xp = x + (size_t)node0 * CIN;
    long long rem = ((long long)tot - node0) * CIN;   // readable elements
    float r0 = 0.f, r1 = 0.f;
    if (lane < rem) r0 = xp[lane];
    if (CIN * 8 > 32 && 32 + lane < rem) r1 = xp[32 + lane];

#pragma unroll
    for (int j = 0; j < 8; ++j) {
        if (node0 + j >= tot) break;
        float acc = bv;
#pragma unroll
        for (int k = 0; k < CIN; ++k) {
            const int idx = j * CIN + k;
            float xv = (idx < 32) ? __shfl_sync(0xffffffffu, r0, idx)
                                  : __shfl_sync(0xffffffffu, r1, idx - 32);
            acc += xv * Wr[k];
        }
        out[(size_t)(node0 + j) * CC + lane] = acc > 0.f ? acc : 0.01f * acc;
    }
}

// Three embeds in one launch; block-range select with scalar args.
__global__ __launch_bounds__(256) void embed_all_kernel(
    const float* xF, const float* WF, const float* bF, float* oF, int bStartE,
    const float* xE, const float* WE, const float* bE, float* oE, int bStartV,
    const float* xV, const float* WV, const float* bV, float* oV) {
    int lane = threadIdx.x & 31, wip = threadIdx.x >> 5;
    int blk = blockIdx.x;
    if (blk < bStartE) {
        embed_body<4>(xF, WF, bF, oF, blk * 8 + wip, BB * NF, lane);
    } else if (blk < bStartV) {
        embed_body<6>(xE, WE, bE, oE, (blk - bStartE) * 8 + wip, BB * NE, lane);
    } else {
        embed_body<3>(xV, WV, bV, oV, (blk - bStartV) * 8 + wip, BB * NV, lane);
    }
}

// Fused segment-min gather + residual MLP. Block = 64 nodes (8 per warp).
// Bucket row via one coalesced LDG + shfl; chain-head prefetch; stage double-
// buffered so only ONE syncwarp per node.
__global__ __launch_bounds__(256, 4) void reduce_mlp_kernel(
    const int* __restrict__ cnt, const int* __restrict__ bucket,
    const float* __restrict__ xs, const float* __restrict__ xd,
    const float* __restrict__ W, const float* __restrict__ bias,
    float* __restrict__ out, int Ns, int Nd) {
    __shared__ unsigned long long sWp[CC][CC];            // [k][lane] = (W[k][lane], W[k+32][lane])
    __shared__ __align__(16) float2 stage[2][8][BB][CC];  // double-buffered [buf][warp][batch][k]
    int tid = threadIdx.x;
    int lane = tid & 31, wip = tid >> 5;

    for (int k = wip; k < CC; k += 8)
        sWp[k][lane] = pack2(W[k * CC + lane], W[(k + CC) * CC + lane]);
    __syncthreads();

    float bv = bias[lane];
    const size_t BS = (size_t)Ns * CC;
    const float PINF = __int_as_float(0x7f800000);

    int dBase = blockIdx.x * 64 + wip * 8;

    int degN = 0, bkvN = 0;
    if (dBase < Nd) {
        degN = cnt[dBase];
        bkvN = bucket[(size_t)dBase * CAP + lane];
    }

#pragma unroll 1
    for (int it = 0; it < 8; ++it) {
        int d = dBase + it;
        if (d >= Nd) break;

        int deg = degN;
        if (deg > CAP) deg = CAP;
        int bkv = bkvN;

        if (it < 7 && d + 1 < Nd) {
            degN = cnt[d + 1];
            bkvN = bucket[(size_t)(d + 1) * CAP + lane];
        }

        float xv[BB];
#pragma unroll
        for (int b = 0; b < BB; ++b)
            xv[b] = xd[((size_t)b * Nd + d) * CC + lane];

        // ---- segment-min gather: src indices via shfl, all LDGs independent ----
        float mn0 = PINF, mn1 = PINF, mn2 = PINF, mn3 = PINF;
        int i = 0;
        for (; i + 4 <= deg; i += 4) {
            int s0 = __shfl_sync(0xffffffffu, bkv, i);
            int s1 = __shfl_sync(0xffffffffu, bkv, i + 1);
            int s2 = __shfl_sync(0xffffffffu, bkv, i + 2);
            int s3 = __shfl_sync(0xffffffffu, bkv, i + 3);
            const float* p0 = xs + (size_t)s0 * CC + lane;
            const float* p1 = xs + (size_t)s1 * CC + lane;
            const float* p2 = xs + (size_t)s2 * CC + lane;
            const float* p3 = xs + (size_t)s3 * CC + lane;
            float a0 = p0[0],      a1 = p1[0],      a2 = p2[0],      a3 = p3[0];
            float b0 = p0[BS],     b1 = p1[BS],     b2 = p2[BS],     b3 = p3[BS];
            float c0 = p0[2 * BS], c1 = p1[2 * BS], c2 = p2[2 * BS], c3 = p3[2 * BS];
            float e0 = p0[3 * BS], e1 = p1[3 * BS], e2 = p2[3 * BS], e3 = p3[3 * BS];
            mn0 = fminf(mn0, fminf(fminf(a0, a1), fminf(a2, a3)));
            mn1 = fminf(mn1, fminf(fminf(b0, b1), fminf(b2, b3)));
            mn2 = fminf(mn2, fminf(fminf(c0, c1), fminf(c2, c3)));
            mn3 = fminf(mn3, fminf(fminf(e0, e1), fminf(e2, e3)));
        }
        for (; i < deg; ++i) {
            int s = __shfl_sync(0xffffffffu, bkv, i);
            const float* p = xs + (size_t)s * CC + lane;
            mn0 = fminf(mn0, p[0]);
            mn1 = fminf(mn1, p[BS]);
            mn2 = fminf(mn2, p[2 * BS]);
            mn3 = fminf(mn3, p[3 * BS]);
        }
        float mns[BB] = {mn0, mn1, mn2, mn3};

        // ---- stage h = (xv, mv) per batch (alternate buffers; 1 syncwarp/node) ----
        int buf = it & 1;
#pragma unroll
        for (int b = 0; b < BB; ++b) {
            float m = mns[b];
            float mv = (__float_as_uint(m) == 0x7f800000u) ? 0.f : xv[b] - m;
            stage[buf][wip][b][lane] = make_float2(xv[b], mv);
        }
        __syncwarp();

        // ---- MLP: register-tile 4 W pairs; h via LDS.128 broadcast ----
        unsigned long long acc0[BB], acc1[BB];
#pragma unroll
        for (int b = 0; b < BB; ++b) { acc0[b] = 0ull; acc1[b] = 0ull; }
#pragma unroll
        for (int kt = 0; kt < CC; kt += 4) {
            unsigned long long w0 = sWp[kt][lane],     w1 = sWp[kt + 1][lane];
            unsigned long long w2 = sWp[kt + 2][lane], w3 = sWp[kt + 3][lane];
#pragma unroll
            for (int b = 0; b < BB; ++b) {
                const ulonglong2* hp2 =
                    reinterpret_cast<const ulonglong2*>(stage[buf][wip][b]);
                ulonglong2 h01 = hp2[kt / 2];
                ulonglong2 h23 = hp2[kt / 2 + 1];
                acc0[b] = ffma2(h01.x, w0, acc0[b]);
                acc1[b] = ffma2(h01.y, w1, acc1[b]);
                acc0[b] = ffma2(h23.x, w2, acc0[b]);
                acc1[b] = ffma2(h23.y, w3, acc1[b]);
            }
        }
#pragma unroll
        for (int b = 0; b < BB; ++b) {
            float l0, h0, l1, h1;
            unpack2(acc0[b], l0, h0);
            unpack2(acc1[b], l1, h1);
            float acc = ((l0 + h0) + (l1 + h1)) + bv;
            float o = xv[b] + (acc > 0.f ? acc : 0.01f * acc);
            out[((size_t)b * Nd + d) * CC + lane] = o;
        }
    }
}

static inline int cdiv(long long a, int b) { return (int)((a + b - 1) / b); }

extern "C" void kernel_launch(void* const* d_in, const int* in_sizes, int n_in,
                              void* d_out, int out_size) {
    const float* x_f = (const float*)d_in[0];
    const float* x_e = (const float*)d_in[1];
    const float* x_v = (const float*)d_in[2];
    // d_in[3] = index_id (identity arange; unused)
    const int* fe = (const int*)d_in[4];
    const int* ev = (const int*)d_in[5];
    const int* ff = (const int*)d_in[6];
    const int* ef = (const int*)d_in[7];
    const int* ve = (const int*)d_in[8];
    const float* Wf = (const float*)d_in[9];   const float* bf = (const float*)d_in[10];
    const float* We = (const float*)d_in[11];  const float* be = (const float*)d_in[12];
    const float* Wv = (const float*)d_in[13];  const float* bv = (const float*)d_in[14];
    const float* W_f2e = (const float*)d_in[15]; const float* b_f2e = (const float*)d_in[16];
    const float* W_e2v = (const float*)d_in[17]; const float* b_e2v = (const float*)d_in[18];
    const float* W_ff  = (const float*)d_in[19]; const float* b_ff  = (const float*)d_in[20];
    const float* W_e2f = (const float*)d_in[21]; const float* b_e2f = (const float*)d_in[22];
    const float* W_v2e = (const float*)d_in[23]; const float* b_v2e = (const float*)d_in[24];

    int E_fe = in_sizes[4] / 2, E_ev = in_sizes[5] / 2, E_ff = in_sizes[6] / 2,
        E_ef = in_sizes[7] / 2, E_ve = in_sizes[8] / 2;

    float* out_xf = (float*)d_out;
    float* out_xe = out_xf + (size_t)BB * NF * CC;
    float* out_xv = out_xe + (size_t)BB * NE * CC;

    float *xf0, *xe0, *xv0, *xe1, *xf1;
    int *cnt, *bucket;
    cudaGetSymbolAddress((void**)&xf0, g_xf0);
    cudaGetSymbolAddress((void**)&xe0, g_xe0);
    cudaGetSymbolAddress((void**)&xv0, g_xv0);
    cudaGetSymbolAddress((void**)&xe1, g_xe1);
    cudaGetSymbolAddress((void**)&xf1, g_xf1);
    cudaGetSymbolAddress((void**)&cnt, g_cnt);
    cudaGetSymbolAddress((void**)&bucket, g_bucket);

    const int TB = 256;

    // ---- zero all counters, then build all 5 buckets in ONE launch ----
    zero_cnt_kernel<<<cdiv(CNT_TOT / 4, TB), TB>>>(cnt, CNT_TOT / 4);
    int bA = 0;
    int bB = bA + cdiv(E_fe / 4, TB);
    int bC = bB + cdiv(E_ev / 4, TB);
    int bD = bC + cdiv(E_ff / 4, TB);
    int bE = bD + cdiv(E_ef / 4, TB);
    int bTot = bE + cdiv(E_ve / 4, TB);
    fill_all_kernel<<<bTot, TB>>>(
        fe, E_fe, OFF_F2E, bA,
        ev, E_ev, OFF_E2V, bB,
        ff, E_ff, OFF_FF,  bC,
        ef, E_ef, OFF_E2F, bD,
        ve, E_ve, OFF_V2E,
        cnt, bucket);

    // ---- all three embeddings in ONE launch (8 nodes/warp, 8 warps/block) ----
    int ebF = cdiv(BB * NF, 64);            // blocks for faces
    int ebE = cdiv(BB * NE, 64);            // blocks for edges
    int ebV = cdiv(BB * NV, 64);            // blocks for verts
    embed_all_kernel<<<ebF + ebE + ebV, TB>>>(
        x_f, Wf, bf, xf0, ebF,
        x_e, We, be, xe0, ebF + ebE,
        x_v, Wv, bv, xv0);

    // ---- layers ----
    reduce_mlp_kernel<<<cdiv(NE, 64), 256>>>(cnt + OFF_F2E, bucket + (size_t)OFF_F2E * CAP,
                                             xf0, xe0, W_f2e, b_f2e, xe1, NF, NE);
    reduce_mlp_kernel<<<cdiv(NV, 64), 256>>>(cnt + OFF_E2V, bucket + (size_t)OFF_E2V * CAP,
                                             xe0, xv0, W_e2v, b_e2v, out_xv, NE, NV);
    reduce_mlp_kernel<<<cdiv(NF, 64), 256>>>(cnt + OFF_FF, bucket + (size_t)OFF_FF * CAP,
                                             xf0, xf0, W_ff, b_ff, xf1, NF, NF);
    reduce_mlp_kernel<<<cdiv(NF, 64), 256>>>(cnt + OFF_E2F, bucket + (size_t)OFF_E2F * CAP,
                                             xe1, xf1, W_e2f, b_e2f, out_xf, NE, NF);
    reduce_mlp_kernel<<<cdiv(NE, 64), 256>>>(cnt + OFF_V2E, bucket + (size_t)OFF_V2E * CAP,
                                             out_xv, xe1, W_v2e, b_v2e, out_xe, NV, NE);
}

// round 15
// speedup vs baseline: 1.4256x; 1.2412x over previous
#include <cuda_runtime.h>

#define BB 4
#define CC 32
#define NF 40000
#define NE 80000
#define NV 40000
#define CAP 32          // bucket row = 32 ints = exactly one warp-coalesced load

// cnt layout: [f2e: NE][e2v: NV][ff: NF][e2f: NF][v2e: NE]
#define CNT_TOT (NE + NV + NF + NF + NE)
#define OFF_F2E 0
#define OFF_E2V (NE)
#define OFF_FF  (NE + NV)
#define OFF_E2F (NE + NV + NF)
#define OFF_V2E (NE + NV + NF + NF)

// Persistent scratch (no allocations anywhere); canonical [b][node][c] layout.
__device__ float g_xf0[BB * NF * CC];
__device__ float g_xe0[BB * NE * CC];
__device__ float g_xv0[BB * NV * CC];
__device__ float g_xe1[BB * NE * CC];   // F2E output
__device__ float g_xf1[BB * NF * CC];   // FF output
__device__ int   g_cnt[CNT_TOT];
__device__ int   g_bucket[(size_t)CNT_TOT * CAP];

__device__ __forceinline__ unsigned long long ffma2(
    unsigned long long a, unsigned long long b, unsigned long long c) {
    unsigned long long d;
    asm("fma.rn.f32x2 %0, %1, %2, %3;" : "=l"(d) : "l"(a), "l"(b), "l"(c));
    return d;
}
__device__ __forceinline__ unsigned long long pack2(float lo, float hi) {
    unsigned long long u;
    asm("mov.b64 %0, {%1, %2};" : "=l"(u) : "f"(lo), "f"(hi));
    return u;
}
__device__ __forceinline__ void unpack2(unsigned long long u, float& lo, float& hi) {
    asm("mov.b64 {%0, %1}, %2;" : "=f"(lo), "=f"(hi) : "l"(u));
}

__global__ void zero_cnt_kernel(int* __restrict__ cnt, int n4) {
    int i = blockIdx.x * blockDim.x + threadIdx.x;
    if (i < n4) reinterpret_cast<int4*>(cnt)[i] = make_int4(0, 0, 0, 0);
}

// All 5 edge lists in one launch. Block-range if/else with SCALAR pointers.
__global__ void fill_all_kernel(
    const int* eA, int EA, int offA, int bA,
    const int* eB, int EB, int offB, int bB,
    const int* eC, int EC, int offC, int bC,
    const int* eD, int ED, int offD, int bD,
    const int* eE, int EE, int offE,
    int* __restrict__ cnt, int* __restrict__ bucket) {
    int blk = blockIdx.x;
    const int* eg; int E; int off; int blk0;
    if      (blk < bB) { eg = eA; E = EA; off = offA; blk0 = bA; }
    else if (blk < bC) { eg = eB; E = EB; off = offB; blk0 = bB; }
    else if (blk < bD) { eg = eC; E = EC; off = offC; blk0 = bC; }
    else if (blk < bD + ((ED / 4 + 255) / 256)) { eg = eD; E = ED; off = offD; blk0 = bD; }
    else { eg = eE; E = EE; off = offE; blk0 = bD + ((ED / 4 + 255) / 256); }
    int i0 = ((blk - blk0) * 256 + threadIdx.x) * 4;
    if (i0 >= E) return;
    int4 s4 = *reinterpret_cast<const int4*>(eg + i0);
    int4 d4 = *reinterpret_cast<const int4*>(eg + E + i0);
    int ss[4] = {s4.x, s4.y, s4.z, s4.w};
    int dd[4] = {d4.x, d4.y, d4.z, d4.w};
#pragma unroll
    for (int j = 0; j < 4; ++j) {
        int d = off + dd[j];
        int slot = atomicAdd(&cnt[d], 1);
        if (slot < CAP) bucket[(size_t)d * CAP + slot] = ss[j];
    }
}

// 8 nodes per warp: 2 coalesced LDGs fetch 8*CIN inputs, distributed by
// compile-time shfl; W column + bias in registers (loaded once per warp).
template <int CIN>
__device__ __forceinline__ void embed_body(
    const float* __restrict__ x, const float* __restrict__ W,
    const float* __restrict__ bias, float* __restrict__ out,
    int warpInSeg, int tot /* BB*nNodes */, int lane) {
    int node0 = warpInSeg * 8;
    if (node0 >= tot) return;
    float Wr[CIN];
#pragma unroll
    for (int k = 0; k < CIN; ++k) Wr[k] = W[k * CC + lane];
    float bv = bias[lane];

    const float* xp = x + (size_t)node0 * CIN;
    long long rem = ((long long)tot - node0) * CIN;   // readable elements
    float r0 = 0.f, r1 = 0.f;
    if (lane < rem) r0 = xp[lane];
    if (CIN * 8 > 32 && 32 + lane < rem) r1 = xp[32 + lane];

#pragma unroll
    for (int j = 0; j < 8; ++j) {
        if (node0 + j >= tot) break;
        float acc = bv;
#pragma unroll
        for (int k = 0; k < CIN; ++k) {
            const int idx = j * CIN + k;
            float xv = (idx < 32) ? __shfl_sync(0xffffffffu, r0, idx)
                                  : __shfl_sync(0xffffffffu, r1, idx - 32);
            acc += xv * Wr[k];
        }
        out[(size_t)(node0 + j) * CC + lane] = acc > 0.f ? acc : 0.01f * acc;
    }
}

// Three embeds in one launch; block-range select with scalar args.
__global__ __launch_bounds__(256) void embed_all_kernel(
    const float* xF, const float* WF, const float* bF, float* oF, int bStartE,
    const float* xE, const float* WE, const float* bE, float* oE, int bStartV,
    const float* xV, const float* WV, const float* bV, float* oV) {
    int lane = threadIdx.x & 31, wip = threadIdx.x >> 5;
    int blk = blockIdx.x;
    if (blk < bStartE) {
        embed_body<4>(xF, WF, bF, oF, blk * 8 + wip, BB * NF, lane);
    } else if (blk < bStartV) {
        embed_body<6>(xE, WE, bE, oE, (blk - bStartE) * 8 + wip, BB * NE, lane);
    } else {
        embed_body<3>(xV, WV, bV, oV, (blk - bStartV) * 8 + wip, BB * NV, lane);
    }
}

// Batched fused segment-min gather + residual MLP (up to 3 layers per launch,
// block picks its layer by grid range — uniform per block, LDC-resident params).
// Block = 64 nodes (8 per warp). Bucket row via one coalesced LDG + shfl;
// chain-head prefetch; stage double-buffered (1 syncwarp/node).
// Single accumulator chain + 2-wide W tile to fit 5-block occupancy.
struct Layer {
    const int* cnt; const int* bucket;
    const float* xs; const float* xd;
    const float* W; const float* bias;
    float* out;
    int Ns, Nd;
    int blockStart;
};
struct PhaseParams { Layer L[3]; int n; };

__global__ __launch_bounds__(256, 5) void reduce_mlp_batched(PhaseParams pp) {
    __shared__ unsigned long long sWp[CC][CC];            // [k][lane] = (W[k][lane], W[k+32][lane])
    __shared__ __align__(16) float2 stage[2][8][BB][CC];  // [buf][warp][batch][k]
    int tid = threadIdx.x;
    int lane = tid & 31, wip = tid >> 5;

    int li = 0;
    if (pp.n > 1 && (int)blockIdx.x >= pp.L[1].blockStart) li = 1;
    if (pp.n > 2 && (int)blockIdx.x >= pp.L[2].blockStart) li = 2;
    const int* __restrict__ cnt = pp.L[li].cnt;
    const int* __restrict__ bucket = pp.L[li].bucket;
    const float* __restrict__ xs = pp.L[li].xs;
    const float* __restrict__ xd = pp.L[li].xd;
    const float* __restrict__ W = pp.L[li].W;
    float* __restrict__ out = pp.L[li].out;
    const int Ns = pp.L[li].Ns, Nd = pp.L[li].Nd;
    const int blockStart = pp.L[li].blockStart;

    for (int k = wip; k < CC; k += 8)
        sWp[k][lane] = pack2(W[k * CC + lane], W[(k + CC) * CC + lane]);
    __syncthreads();

    float bv = pp.L[li].bias[lane];
    const size_t BS = (size_t)Ns * CC;
    const float PINF = __int_as_float(0x7f800000);

    int dBase = ((int)blockIdx.x - blockStart) * 64 + wip * 8;

    int degN = 0, bkvN = 0;
    if (dBase < Nd) {
        degN = cnt[dBase];
        bkvN = bucket[(size_t)dBase * CAP + lane];
    }

#pragma unroll 1
    for (int it = 0; it < 8; ++it) {
        int d = dBase + it;
        if (d >= Nd) break;

        int deg = degN;
        if (deg > CAP) deg = CAP;
        int bkv = bkvN;

        if (it < 7 && d + 1 < Nd) {
            degN = cnt[d + 1];
            bkvN = bucket[(size_t)(d + 1) * CAP + lane];
        }

        float xv[BB];
#pragma unroll
        for (int b = 0; b < BB; ++b)
            xv[b] = xd[((size_t)b * Nd + d) * CC + lane];

        // ---- segment-min gather: src indices via shfl, all LDGs independent ----
        float mn0 = PINF, mn1 = PINF, mn2 = PINF, mn3 = PINF;
        int i = 0;
        for (; i + 4 <= deg; i += 4) {
            int s0 = __shfl_sync(0xffffffffu, bkv, i);
            int s1 = __shfl_sync(0xffffffffu, bkv, i + 1);
            int s2 = __shfl_sync(0xffffffffu, bkv, i + 2);
            int s3 = __shfl_sync(0xffffffffu, bkv, i + 3);
            const float* p0 = xs + (size_t)s0 * CC + lane;
            const float* p1 = xs + (size_t)s1 * CC + lane;
            const float* p2 = xs + (size_t)s2 * CC + lane;
            const float* p3 = xs + (size_t)s3 * CC + lane;
            float a0 = p0[0],      a1 = p1[0],      a2 = p2[0],      a3 = p3[0];
            float b0 = p0[BS],     b1 = p1[BS],     b2 = p2[BS],     b3 = p3[BS];
            float c0 = p0[2 * BS], c1 = p1[2 * BS], c2 = p2[2 * BS], c3 = p3[2 * BS];
            float e0 = p0[3 * BS], e1 = p1[3 * BS], e2 = p2[3 * BS], e3 = p3[3 * BS];
            mn0 = fminf(mn0, fminf(fminf(a0, a1), fminf(a2, a3)));
            mn1 = fminf(mn1, fminf(fminf(b0, b1), fminf(b2, b3)));
            mn2 = fminf(mn2, fminf(fminf(c0, c1), fminf(c2, c3)));
            mn3 = fminf(mn3, fminf(fminf(e0, e1), fminf(e2, e3)));
        }
        for (; i < deg; ++i) {
            int s = __shfl_sync(0xffffffffu, bkv, i);
            const float* p = xs + (size_t)s * CC + lane;
            mn0 = fminf(mn0, p[0]);
            mn1 = fminf(mn1, p[BS]);
            mn2 = fminf(mn2, p[2 * BS]);
            mn3 = fminf(mn3, p[3 * BS]);
        }
        float mns[BB] = {mn0, mn1, mn2, mn3};

        // ---- stage h = (xv, mv) per batch (alternate buffers; 1 syncwarp/node) ----
        int buf = it & 1;
#pragma unroll
        for (int b = 0; b < BB; ++b) {
            float m = mns[b];
            float mv = (__float_as_uint(m) == 0x7f800000u) ? 0.f : xv[b] - m;
            stage[buf][wip][b][lane] = make_float2(xv[b], mv);
        }
        __syncwarp();

        // ---- MLP: 2-wide W tile, single acc chain per batch ----
        unsigned long long acc[BB];
#pragma unroll
        for (int b = 0; b < BB; ++b) acc[b] = 0ull;
#pragma unroll
        for (int kt = 0; kt < CC; kt += 2) {
            unsigned long long w0 = sWp[kt][lane], w1 = sWp[kt + 1][lane];
#pragma unroll
            for (int b = 0; b < BB; ++b) {
                ulonglong2 h01 = *reinterpret_cast<const ulonglong2*>(
                    &stage[buf][wip][b][kt]);
                acc[b] = ffma2(h01.x, w0, acc[b]);
                acc[b] = ffma2(h01.y, w1, acc[b]);
            }
        }
#pragma unroll
        for (int b = 0; b < BB; ++b) {
            float lo, hi;
            unpack2(acc[b], lo, hi);
            float a = (lo + hi) + bv;
            float o = xv[b] + (a > 0.f ? a : 0.01f * a);
            out[((size_t)b * Nd + d) * CC + lane] = o;
        }
    }
}

static inline int cdiv(long long a, int b) { return (int)((a + b - 1) / b); }

extern "C" void kernel_launch(void* const* d_in, const int* in_sizes, int n_in,
                              void* d_out, int out_size) {
    const float* x_f = (const float*)d_in[0];
    const float* x_e = (const float*)d_in[1];
    const float* x_v = (const float*)d_in[2];
    // d_in[3] = index_id (identity arange; unused)
    const int* fe = (const int*)d_in[4];
    const int* ev = (const int*)d_in[5];
    const int* ff = (const int*)d_in[6];
    const int* ef = (const int*)d_in[7];
    const int* ve = (const int*)d_in[8];
    const float* Wf = (const float*)d_in[9];   const float* bf = (const float*)d_in[10];
    const float* We = (const float*)d_in[11];  const float* be = (const float*)d_in[12];
    const float* Wv = (const float*)d_in[13];  const float* bv = (const float*)d_in[14];
    const float* W_f2e = (const float*)d_in[15]; const float* b_f2e = (const float*)d_in[16];
    const float* W_e2v = (const float*)d_in[17]; const float* b_e2v = (const float*)d_in[18];
    const float* W_ff  = (const float*)d_in[19]; const float* b_ff  = (const float*)d_in[20];
    const float* W_e2f = (const float*)d_in[21]; const float* b_e2f = (const float*)d_in[22];
    const float* W_v2e = (const float*)d_in[23]; const float* b_v2e = (const float*)d_in[24];

    int E_fe = in_sizes[4] / 2, E_ev = in_sizes[5] / 2, E_ff = in_sizes[6] / 2,
        E_ef = in_sizes[7] / 2, E_ve = in_sizes[8] / 2;

    float* out_xf = (float*)d_out;
    float* out_xe = out_xf + (size_t)BB * NF * CC;
    float* out_xv = out_xe + (size_t)BB * NE * CC;

    float *xf0, *xe0, *xv0, *xe1, *xf1;
    int *cnt, *bucket;
    cudaGetSymbolAddress((void**)&xf0, g_xf0);
    cudaGetSymbolAddress((void**)&xe0, g_xe0);
    cudaGetSymbolAddress((void**)&xv0, g_xv0);
    cudaGetSymbolAddress((void**)&xe1, g_xe1);
    cudaGetSymbolAddress((void**)&xf1, g_xf1);
    cudaGetSymbolAddress((void**)&cnt, g_cnt);
    cudaGetSymbolAddress((void**)&bucket, g_bucket);

    const int TB = 256;

    // ---- zero all counters, then build all 5 buckets in ONE launch ----
    zero_cnt_kernel<<<cdiv(CNT_TOT / 4, TB), TB>>>(cnt, CNT_TOT / 4);
    int bA = 0;
    int bB = bA + cdiv(E_fe / 4, TB);
    int bC = bB + cdiv(E_ev / 4, TB);
    int bD = bC + cdiv(E_ff / 4, TB);
    int bE = bD + cdiv(E_ef / 4, TB);
    int bTot = bE + cdiv(E_ve / 4, TB);
    fill_all_kernel<<<bTot, TB>>>(
        fe, E_fe, OFF_F2E, bA,
        ev, E_ev, OFF_E2V, bB,
        ff, E_ff, OFF_FF,  bC,
        ef, E_ef, OFF_E2F, bD,
        ve, E_ve, OFF_V2E,
        cnt, bucket);

    // ---- all three embeddings in ONE launch (8 nodes/warp, 8 warps/block) ----
    int ebF = cdiv(BB * NF, 64);
    int ebE = cdiv(BB * NE, 64);
    int ebV = cdiv(BB * NV, 64);
    embed_all_kernel<<<ebF + ebE + ebV, TB>>>(
        x_f, Wf, bf, xf0, ebF,
        x_e, We, be, xe0, ebF + ebE,
        x_v, Wv, bv, xv0);

    // ---- Phase B: F2E + E2V + FF in one launch ----
    PhaseParams pb;
    pb.n = 3;
    pb.L[0] = { cnt + OFF_F2E, bucket + (size_t)OFF_F2E * CAP, xf0, xe0,
                W_f2e, b_f2e, xe1, NF, NE, 0 };
    pb.L[1] = { cnt + OFF_E2V, bucket + (size_t)OFF_E2V * CAP, xe0, xv0,
                W_e2v, b_e2v, out_xv, NE, NV, cdiv(NE, 64) };
    pb.L[2] = { cnt + OFF_FF, bucket + (size_t)OFF_FF * CAP, xf0, xf0,
                W_ff, b_ff, xf1, NF, NF, cdiv(NE, 64) + cdiv(NV, 64) };
    int nbB = cdiv(NE, 64) + cdiv(NV, 64) + cdiv(NF, 64);
    reduce_mlp_batched<<<nbB, 256>>>(pb);

    // ---- Phase C: E2F + V2E in one launch ----
    PhaseParams pc;
    pc.n = 2;
    pc.L[0] = { cnt + OFF_E2F, bucket + (size_t)OFF_E2F * CAP, xe1, xf1,
                W_e2f, b_e2f, out_xf, NE, NF, 0 };
    pc.L[1] = { cnt + OFF_V2E, bucket + (size_t)OFF_V2E * CAP, out_xv, xe1,
                W_v2e, b_v2e, out_xe, NV, NE, cdiv(NF, 64) };
    pc.L[2] = pc.L[1];   // unused (guarded by pc.n)
    int nbC = cdiv(NF, 64) + cdiv(NE, 64);
    reduce_mlp_batched<<<nbC, 256>>>(pc);
}

// round 16
// speedup vs baseline: 1.5821x; 1.1098x over previous
#include <cuda_runtime.h>

#define BB 4
#define CC 32
#define NF 40000
#define NE 80000
#define NV 40000
#define CAP 32          // bucket row = 32 ints = exactly one warp-coalesced load

// cnt layout: [f2e: NE][e2v: NV][ff: NF][e2f: NF][v2e: NE]
#define CNT_TOT (NE + NV + NF + NF + NE)
#define OFF_F2E 0
#define OFF_E2V (NE)
#define OFF_FF  (NE + NV)
#define OFF_E2F (NE + NV + NF)
#define OFF_V2E (NE + NV + NF + NF)

// Persistent scratch (no allocations anywhere); canonical [b][node][c] layout.
__device__ float g_xf0[BB * NF * CC];
__device__ float g_xe0[BB * NE * CC];
__device__ float g_xv0[BB * NV * CC];
__device__ float g_xe1[BB * NE * CC];   // F2E output
__device__ float g_xf1[BB * NF * CC];   // FF output
__device__ int   g_cnt[CNT_TOT];
__device__ int   g_bucket[(size_t)CNT_TOT * CAP];

__device__ __forceinline__ unsigned long long ffma2(
    unsigned long long a, unsigned long long b, unsigned long long c) {
    unsigned long long d;
    asm("fma.rn.f32x2 %0, %1, %2, %3;" : "=l"(d) : "l"(a), "l"(b), "l"(c));
    return d;
}
__device__ __forceinline__ unsigned long long pack2(float lo, float hi) {
    unsigned long long u;
    asm("mov.b64 %0, {%1, %2};" : "=l"(u) : "f"(lo), "f"(hi));
    return u;
}
__device__ __forceinline__ void unpack2(unsigned long long u, float& lo, float& hi) {
    asm("mov.b64 {%0, %1}, %2;" : "=f"(lo), "=f"(hi) : "l"(u));
}

__global__ void zero_cnt_kernel(int* __restrict__ cnt, int n4) {
    int i = blockIdx.x * blockDim.x + threadIdx.x;
    if (i < n4) reinterpret_cast<int4*>(cnt)[i] = make_int4(0, 0, 0, 0);
}

// All 5 edge lists in one launch. Block-range if/else with SCALAR pointers.
__global__ void fill_all_kernel(
    const int* eA, int EA, int offA, int bA,
    const int* eB, int EB, int offB, int bB,
    const int* eC, int EC, int offC, int bC,
    const int* eD, int ED, int offD, int bD,
    const int* eE, int EE, int offE,
    int* __restrict__ cnt, int* __restrict__ bucket) {
    int blk = blockIdx.x;
    const int* eg; int E; int off; int blk0;
    if      (blk < bB) { eg = eA; E = EA; off = offA; blk0 = bA; }
    else if (blk < bC) { eg = eB; E = EB; off = offB; blk0 = bB; }
    else if (blk < bD) { eg = eC; E = EC; off = offC; blk0 = bC; }
    else if (blk < bD + ((ED / 4 + 255) / 256)) { eg = eD; E = ED; off = offD; blk0 = bD; }
    else { eg = eE; E = EE; off = offE; blk0 = bD + ((ED / 4 + 255) / 256); }
    int i0 = ((blk - blk0) * 256 + threadIdx.x) * 4;
    if (i0 >= E) return;
    int4 s4 = *reinterpret_cast<const int4*>(eg + i0);
    int4 d4 = *reinterpret_cast<const int4*>(eg + E + i0);
    int ss[4] = {s4.x, s4.y, s4.z, s4.w};
    int dd[4] = {d4.x, d4.y, d4.z, d4.w};
#pragma unroll
    for (int j = 0; j < 4; ++j) {
        int d = off + dd[j];
        int slot = atomicAdd(&cnt[d], 1);
        if (slot < CAP) bucket[(size_t)d * CAP + slot] = ss[j];
    }
}

// 8 nodes per warp: 2 coalesced LDGs fetch 8*CIN inputs, distributed by
// compile-time shfl; W column + bias in registers (loaded once per warp).
template <int CIN>
__device__ __forceinline__ void embed_body(
    const float* __restrict__ x, const float* __restrict__ W,
    const float* __restrict__ bias, float* __restrict__ out,
    int warpInSeg, int tot /* BB*nNodes */, int lane) {
    int node0 = warpInSeg * 8;
    if (node0 >= tot) return;
    float Wr[CIN];
#pragma unroll
    for (int k = 0; k < CIN; ++k) Wr[k] = W[k * CC + lane];
    float bv = bias[lane];

    const float* xp = x + (size_t)node0 * CIN;
    long long rem = ((long long)tot - node0) * CIN;   // readable elements
    float r0 = 0.f, r1 = 0.f;
    if (lane < rem) r0 = xp[lane];
    if (CIN * 8 > 32 && 32 + lane < rem) r1 = xp[32 + lane];

#pragma unroll
    for (int j = 0; j < 8; ++j) {
        if (node0 + j >= tot) break;
        float acc = bv;
#pragma unroll
        for (int k = 0; k < CIN; ++k) {
            const int idx = j * CIN + k;
            float xv = (idx < 32) ? __shfl_sync(0xffffffffu, r0, idx)
                                  : __shfl_sync(0xffffffffu, r1, idx - 32);
            acc += xv * Wr[k];
        }
        out[(size_t)(node0 + j) * CC + lane] = acc > 0.f ? acc : 0.01f * acc;
    }
}

// Three embeds in one launch; block-range select with scalar args.
__global__ __launch_bounds__(256) void embed_all_kernel(
    const float* xF, const float* WF, const float* bF, float* oF, int bStartE,
    const float* xE, const float* WE, const float* bE, float* oE, int bStartV,
    const float* xV, const float* WV, const float* bV, float* oV) {
    int lane = threadIdx.x & 31, wip = threadIdx.x >> 5;
    int blk = blockIdx.x;
    if (blk < bStartE) {
        embed_body<4>(xF, WF, bF, oF, blk * 8 + wip, BB * NF, lane);
    } else if (blk < bStartV) {
        embed_body<6>(xE, WE, bE, oE, (blk - bStartE) * 8 + wip, BB * NE, lane);
    } else {
        embed_body<3>(xV, WV, bV, oV, (blk - bStartV) * 8 + wip, BB * NV, lane);
    }
}

// Batched fused segment-min gather + residual MLP (up to 3 layers per launch).
// Block = 64 nodes; warp = 8 nodes processed as 4 PAIRS: both nodes of a pair
// are gathered+staged, then ONE joint MLP pass shares each W smem load across
// 2 nodes x 4 batches (halves the dominant W LDS wavefront stream; ncu R15:
// L1 88.8%). xv is re-read from stage at the epilogue to keep regs <= 51
// (5-block occupancy). All Nd are divisible by 64 -> every warp fully populated.
struct Layer {
    const int* cnt; const int* bucket;
    const float* xs; const float* xd;
    const float* W; const float* bias;
    float* out;
    int Ns, Nd;
    int blockStart;
};
struct PhaseParams { Layer L[3]; int n; };

__global__ __launch_bounds__(256, 5) void reduce_mlp_batched(PhaseParams pp) {
    __shared__ unsigned long long sWp[CC][CC];            // [k][lane] = (W[k][lane], W[k+32][lane])
    __shared__ __align__(16) float2 stage[2][8][BB][CC];  // [nodeInPair][warp][batch][k]
    int tid = threadIdx.x;
    int lane = tid & 31, wip = tid >> 5;

    int li = 0;
    if (pp.n > 1 && (int)blockIdx.x >= pp.L[1].blockStart) li = 1;
    if (pp.n > 2 && (int)blockIdx.x >= pp.L[2].blockStart) li = 2;
    const int* __restrict__ cnt = pp.L[li].cnt;
    const int* __restrict__ bucket = pp.L[li].bucket;
    const float* __restrict__ xs = pp.L[li].xs;
    const float* __restrict__ xd = pp.L[li].xd;
    const float* __restrict__ W = pp.L[li].W;
    float* __restrict__ out = pp.L[li].out;
    const int Ns = pp.L[li].Ns, Nd = pp.L[li].Nd;

    for (int k = wip; k < CC; k += 8)
        sWp[k][lane] = pack2(W[k * CC + lane], W[(k + CC) * CC + lane]);
    __syncthreads();

    float bv = pp.L[li].bias[lane];
    const size_t BS = (size_t)Ns * CC;
    const float PINF = __int_as_float(0x7f800000);

    int dBase = ((int)blockIdx.x - pp.L[li].blockStart) * 64 + wip * 8;
    if (dBase >= Nd) return;   // safety (Nd % 64 == 0 -> never taken)

    // Prefetch chain-heads for pair 0.
    int pdeg0 = cnt[dBase],     pdeg1 = cnt[dBase + 1];
    int pbkv0 = bucket[(size_t)dBase * CAP + lane];
    int pbkv1 = bucket[(size_t)(dBase + 1) * CAP + lane];

#pragma unroll 1
    for (int p = 0; p < 4; ++p) {
        int dA = dBase + 2 * p;
        int cdeg[2] = {pdeg0, pdeg1};
        int cbkv[2] = {pbkv0, pbkv1};
        if (p < 3) {
            pdeg0 = cnt[dA + 2];
            pdeg1 = cnt[dA + 3];
            pbkv0 = bucket[(size_t)(dA + 2) * CAP + lane];
            pbkv1 = bucket[(size_t)(dA + 3) * CAP + lane];
        }

        // ---- gather + stage both nodes of the pair ----
#pragma unroll
        for (int n = 0; n < 2; ++n) {
            int d = dA + n;
            int deg = cdeg[n] > CAP ? CAP : cdeg[n];
            int bkv = cbkv[n];

            float xv0 = xd[((size_t)0 * Nd + d) * CC + lane];
            float xv1 = xd[((size_t)1 * Nd + d) * CC + lane];
            float xv2 = xd[((size_t)2 * Nd + d) * CC + lane];
            float xv3 = xd[((size_t)3 * Nd + d) * CC + lane];

            float mn0 = PINF, mn1 = PINF, mn2 = PINF, mn3 = PINF;
            int i = 0;
            for (; i + 4 <= deg; i += 4) {
                int s0 = __shfl_sync(0xffffffffu, bkv, i);
                int s1 = __shfl_sync(0xffffffffu, bkv, i + 1);
                int s2 = __shfl_sync(0xffffffffu, bkv, i + 2);
                int s3 = __shfl_sync(0xffffffffu, bkv, i + 3);
                const float* p0 = xs + (size_t)s0 * CC + lane;
                const float* p1 = xs + (size_t)s1 * CC + lane;
                const float* p2 = xs + (size_t)s2 * CC + lane;
                const float* p3 = xs + (size_t)s3 * CC + lane;
                float a0 = p0[0],      a1 = p1[0],      a2 = p2[0],      a3 = p3[0];
                float b0 = p0[BS],     b1 = p1[BS],     b2 = p2[BS],     b3 = p3[BS];
                float c0 = p0[2 * BS], c1 = p1[2 * BS], c2 = p2[2 * BS], c3 = p3[2 * BS];
                float e0 = p0[3 * BS], e1 = p1[3 * BS], e2 = p2[3 * BS], e3 = p3[3 * BS];
                mn0 = fminf(mn0, fminf(fminf(a0, a1), fminf(a2, a3)));
                mn1 = fminf(mn1, fminf(fminf(b0, b1), fminf(b2, b3)));
                mn2 = fminf(mn2, fminf(fminf(c0, c1), fminf(c2, c3)));
                mn3 = fminf(mn3, fminf(fminf(e0, e1), fminf(e2, e3)));
            }
            for (; i < deg; ++i) {
                int s = __shfl_sync(0xffffffffu, bkv, i);
                const float* q = xs + (size_t)s * CC + lane;
                mn0 = fminf(mn0, q[0]);
                mn1 = fminf(mn1, q[BS]);
                mn2 = fminf(mn2, q[2 * BS]);
                mn3 = fminf(mn3, q[3 * BS]);
            }
            float mv0 = (__float_as_uint(mn0) == 0x7f800000u) ? 0.f : xv0 - mn0;
            float mv1 = (__float_as_uint(mn1) == 0x7f800000u) ? 0.f : xv1 - mn1;
            float mv2 = (__float_as_uint(mn2) == 0x7f800000u) ? 0.f : xv2 - mn2;
            float mv3 = (__float_as_uint(mn3) == 0x7f800000u) ? 0.f : xv3 - mn3;
            stage[n][wip][0][lane] = make_float2(xv0, mv0);
            stage[n][wip][1][lane] = make_float2(xv1, mv1);
            stage[n][wip][2][lane] = make_float2(xv2, mv2);
            stage[n][wip][3][lane] = make_float2(xv3, mv3);
        }
        __syncwarp();

        // ---- joint MLP: each W load feeds 2 nodes x 4 batches ----
        unsigned long long acc[2][BB];
#pragma unroll
        for (int n = 0; n < 2; ++n)
#pragma unroll
            for (int b = 0; b < BB; ++b) acc[n][b] = 0ull;
#pragma unroll
        for (int kt = 0; kt < CC; kt += 2) {
            unsigned long long w0 = sWp[kt][lane], w1 = sWp[kt + 1][lane];
#pragma unroll
            for (int n = 0; n < 2; ++n)
#pragma unroll
                for (int b = 0; b < BB; ++b) {
                    ulonglong2 h01 = *reinterpret_cast<const ulonglong2*>(
                        &stage[n][wip][b][kt]);
                    acc[n][b] = ffma2(h01.x, w0, acc[n][b]);
                    acc[n][b] = ffma2(h01.y, w1, acc[n][b]);
                }
        }

        // ---- epilogue (xv re-read from stage to keep regs low) ----
#pragma unroll
        for (int n = 0; n < 2; ++n)
#pragma unroll
            for (int b = 0; b < BB; ++b) {
                float lo, hi;
                unpack2(acc[n][b], lo, hi);
                float a = (lo + hi) + bv;
                float xvr = stage[n][wip][b][lane].x;
                float o = xvr + (a > 0.f ? a : 0.01f * a);
                out[((size_t)b * Nd + (dA + n)) * CC + lane] = o;
            }
        __syncwarp();
    }
}

static inline int cdiv(long long a, int b) { return (int)((a + b - 1) / b); }

extern "C" void kernel_launch(void* const* d_in, const int* in_sizes, int n_in,
                              void* d_out, int out_size) {
    const float* x_f = (const float*)d_in[0];
    const float* x_e = (const float*)d_in[1];
    const float* x_v = (const float*)d_in[2];
    // d_in[3] = index_id (identity arange; unused)
    const int* fe = (const int*)d_in[4];
    const int* ev = (const int*)d_in[5];
    const int* ff = (const int*)d_in[6];
    const int* ef = (const int*)d_in[7];
    const int* ve = (const int*)d_in[8];
    const float* Wf = (const float*)d_in[9];   const float* bf = (const float*)d_in[10];
    const float* We = (const float*)d_in[11];  const float* be = (const float*)d_in[12];
    const float* Wv = (const float*)d_in[13];  const float* bv = (const float*)d_in[14];
    const float* W_f2e = (const float*)d_in[15]; const float* b_f2e = (const float*)d_in[16];
    const float* W_e2v = (const float*)d_in[17]; const float* b_e2v = (const float*)d_in[18];
    const float* W_ff  = (const float*)d_in[19]; const float* b_ff  = (const float*)d_in[20];
    const float* W_e2f = (const float*)d_in[21]; const float* b_e2f = (const float*)d_in[22];
    const float* W_v2e = (const float*)d_in[23]; const float* b_v2e = (const float*)d_in[24];

    int E_fe = in_sizes[4] / 2, E_ev = in_sizes[5] / 2, E_ff = in_sizes[6] / 2,
        E_ef = in_sizes[7] / 2, E_ve = in_sizes[8] / 2;

    float* out_xf = (float*)d_out;
    float* out_xe = out_xf + (size_t)BB * NF * CC;
    float* out_xv = out_xe + (size_t)BB * NE * CC;

    float *xf0, *xe0, *xv0, *xe1, *xf1;
    int *cnt, *bucket;
    cudaGetSymbolAddress((void**)&xf0, g_xf0);
    cudaGetSymbolAddress((void**)&xe0, g_xe0);
    cudaGetSymbolAddress((void**)&xv0, g_xv0);
    cudaGetSymbolAddress((void**)&xe1, g_xe1);
    cudaGetSymbolAddress((void**)&xf1, g_xf1);
    cudaGetSymbolAddress((void**)&cnt, g_cnt);
    cudaGetSymbolAddress((void**)&bucket, g_bucket);

    const int TB = 256;

    // ---- zero all counters, then build all 5 buckets in ONE launch ----
    zero_cnt_kernel<<<cdiv(CNT_TOT / 4, TB), TB>>>(cnt, CNT_TOT / 4);
    int bA = 0;
    int bB = bA + cdiv(E_fe / 4, TB);
    int bC = bB + cdiv(E_ev / 4, TB);
    int bD = bC + cdiv(E_ff / 4, TB);
    int bE = bD + cdiv(E_ef / 4, TB);
    int bTot = bE + cdiv(E_ve / 4, TB);
    fill_all_kernel<<<bTot, TB>>>(
        fe, E_fe, OFF_F2E, bA,
        ev, E_ev, OFF_E2V, bB,
        ff, E_ff, OFF_FF,  bC,
        ef, E_ef, OFF_E2F, bD,
        ve, E_ve, OFF_V2E,
        cnt, bucket);

    // ---- all three embeddings in ONE launch (8 nodes/warp, 8 warps/block) ----
    int ebF = cdiv(BB * NF, 64);
    int ebE = cdiv(BB * NE, 64);
    int ebV = cdiv(BB * NV, 64);
    embed_all_kernel<<<ebF + ebE + ebV, TB>>>(
        x_f, Wf, bf, xf0, ebF,
        x_e, We, be, xe0, ebF + ebE,
        x_v, Wv, bv, xv0);

    // ---- Phase B: F2E + E2V + FF in one launch ----
    PhaseParams pb;
    pb.n = 3;
    pb.L[0] = { cnt + OFF_F2E, bucket + (size_t)OFF_F2E * CAP, xf0, xe0,
                W_f2e, b_f2e, xe1, NF, NE, 0 };
    pb.L[1] = { cnt + OFF_E2V, bucket + (size_t)OFF_E2V * CAP, xe0, xv0,
                W_e2v, b_e2v, out_xv, NE, NV, cdiv(NE, 64) };
    pb.L[2] = { cnt + OFF_FF, bucket + (size_t)OFF_FF * CAP, xf0, xf0,
                W_ff, b_ff, xf1, NF, NF, cdiv(NE, 64) + cdiv(NV, 64) };
    int nbB = cdiv(NE, 64) + cdiv(NV, 64) + cdiv(NF, 64);
    reduce_mlp_batched<<<nbB, 256>>>(pb);

    // ---- Phase C: E2F + V2E in one launch ----
    PhaseParams pc;
    pc.n = 2;
    pc.L[0] = { cnt + OFF_E2F, bucket + (size_t)OFF_E2F * CAP, xe1, xf1,
                W_e2f, b_e2f, out_xf, NE, NF, 0 };
    pc.L[1] = { cnt + OFF_V2E, bucket + (size_t)OFF_V2E * CAP, out_xv, xe1,
                W_v2e, b_v2e, out_xe, NV, NE, cdiv(NF, 64) };
    pc.L[2] = pc.L[1];   // unused (guarded by pc.n)
    int nbC = cdiv(NF, 64) + cdiv(NE, 64);
    reduce_mlp_batched<<<nbC, 256>>>(pc);
}